// round 1
// baseline (speedup 1.0000x reference)
#include <cuda_runtime.h>
#include <cuda_bf16.h>
#include <math.h>

// Problem constants
#define Bq 4
#define Sq 2048
#define Eq 1024

// Scratch (allocation-free rule: __device__ globals)
__device__ float g_q[Bq * Sq * Eq];
__device__ float g_k[Bq * Sq * Eq];
__device__ float g_v[Bq * Sq * Eq];
__device__ float g_s[(size_t)Bq * Sq * Sq];

#define BM 128
#define BN 128
#define BK 8
#define TM 8
#define TN 8
#define NTHREADS 256

// C[M,N] = A[M,K] @ B  where B is [K,N] (TRANS_B=0) or [N,K] (TRANS_B=1, i.e. A@B^T).
// All of M,N divisible by 128, K divisible by 8. Batched via blockIdx.z with strides.
template <int TRANS_B>
__global__ __launch_bounds__(NTHREADS)
void sgemm_kernel(const float* __restrict__ A, const float* __restrict__ B,
                  float* __restrict__ C, int M, int N, int K,
                  long strideA, long strideB, long strideC) {
    __shared__ float As[BK][BM];
    __shared__ float Bs[BK][BN];

    A += (long)blockIdx.z * strideA;
    B += (long)blockIdx.z * strideB;
    C += (long)blockIdx.z * strideC;

    const int tid = threadIdx.x;
    const int m0 = blockIdx.y * BM;
    const int n0 = blockIdx.x * BN;

    // A tile: 128 rows x 8 cols -> one float4 per thread
    const int arow = tid >> 1;          // 0..127
    const int acol = (tid & 1) * 4;     // 0 or 4
    // B tile (NN): 8 rows x 128 cols -> one float4 per thread
    const int brow = tid >> 5;          // 0..7
    const int bcol = (tid & 31) * 4;    // 0..124

    const int trow = (tid >> 4) * TM;   // 0..120
    const int tcol = (tid & 15) * TN;   // 0..120

    float acc[TM][TN];
#pragma unroll
    for (int i = 0; i < TM; i++)
#pragma unroll
        for (int j = 0; j < TN; j++) acc[i][j] = 0.0f;

    for (int k0 = 0; k0 < K; k0 += BK) {
        // load A tile (transpose into As[k][m])
        float4 a = *(const float4*)&A[(long)(m0 + arow) * K + k0 + acol];
        As[acol + 0][arow] = a.x;
        As[acol + 1][arow] = a.y;
        As[acol + 2][arow] = a.z;
        As[acol + 3][arow] = a.w;

        if (TRANS_B) {
            // B is [N,K]: tile 128 n-rows x 8 k-cols, transpose into Bs[k][n]
            float4 b = *(const float4*)&B[(long)(n0 + arow) * K + k0 + acol];
            Bs[acol + 0][arow] = b.x;
            Bs[acol + 1][arow] = b.y;
            Bs[acol + 2][arow] = b.z;
            Bs[acol + 3][arow] = b.w;
        } else {
            // B is [K,N]: tile 8 k-rows x 128 n-cols, direct
            float4 b = *(const float4*)&B[(long)(k0 + brow) * N + n0 + bcol];
            *(float4*)&Bs[brow][bcol] = b;
        }
        __syncthreads();

#pragma unroll
        for (int kk = 0; kk < BK; kk++) {
            float ra[TM], rb[TN];
#pragma unroll
            for (int i = 0; i < TM; i++) ra[i] = As[kk][trow + i];
#pragma unroll
            for (int j = 0; j < TN; j++) rb[j] = Bs[kk][tcol + j];
#pragma unroll
            for (int i = 0; i < TM; i++)
#pragma unroll
                for (int j = 0; j < TN; j++) acc[i][j] = fmaf(ra[i], rb[j], acc[i][j]);
        }
        __syncthreads();
    }

#pragma unroll
    for (int i = 0; i < TM; i++) {
#pragma unroll
        for (int j = 0; j < TN; j += 4) {
            float4 o;
            o.x = acc[i][j + 0];
            o.y = acc[i][j + 1];
            o.z = acc[i][j + 2];
            o.w = acc[i][j + 3];
            *(float4*)&C[(long)(m0 + trow + i) * N + n0 + tcol + j] = o;
        }
    }
}

// Row softmax over rows of length 2048, followed by division by 32 (= sqrt(E)).
// One CTA (256 threads) per row; 8 elements per thread, kept in registers.
__global__ __launch_bounds__(256)
void softmax_scale_kernel(float* __restrict__ S) {
    const int n = Sq;                      // 2048
    float* row = S + (long)blockIdx.x * n;
    const int tid = threadIdx.x;

    float vals[8];
    float m = -INFINITY;
#pragma unroll
    for (int i = 0; i < 8; i++) {
        vals[i] = row[tid + i * 256];
        m = fmaxf(m, vals[i]);
    }

    __shared__ float red[256];
    red[tid] = m;
    __syncthreads();
    for (int s = 128; s > 0; s >>= 1) {
        if (tid < s) red[tid] = fmaxf(red[tid], red[tid + s]);
        __syncthreads();
    }
    m = red[0];
    __syncthreads();

    float sum = 0.0f;
#pragma unroll
    for (int i = 0; i < 8; i++) {
        vals[i] = expf(vals[i] - m);
        sum += vals[i];
    }
    red[tid] = sum;
    __syncthreads();
    for (int s = 128; s > 0; s >>= 1) {
        if (tid < s) red[tid] += red[tid + s];
        __syncthreads();
    }
    const float inv = 1.0f / (red[0] * 32.0f);   // SCALE = sqrt(1024) = 32
#pragma unroll
    for (int i = 0; i < 8; i++) row[tid + i * 256] = vals[i] * inv;
}

extern "C" void kernel_launch(void* const* d_in, const int* in_sizes, int n_in,
                              void* d_out, int out_size) {
    const float* values  = (const float*)d_in[0];
    const float* keys    = (const float*)d_in[1];
    const float* queries = (const float*)d_in[2];
    const float* Wv      = (const float*)d_in[3];
    const float* Wk      = (const float*)d_in[4];
    const float* Wq      = (const float*)d_in[5];
    float* out = (float*)d_out;

    float *q_ptr, *k_ptr, *v_ptr, *s_ptr;
    cudaGetSymbolAddress((void**)&q_ptr, g_q);
    cudaGetSymbolAddress((void**)&k_ptr, g_k);
    cudaGetSymbolAddress((void**)&v_ptr, g_v);
    cudaGetSymbolAddress((void**)&s_ptr, g_s);

    // 1) Projections: [8192,1024] = [8192,1024] @ [1024,1024]  (NN)
    {
        dim3 grid(Eq / BN, (Bq * Sq) / BM, 1);
        sgemm_kernel<0><<<grid, NTHREADS>>>(queries, Wq, q_ptr, Bq * Sq, Eq, Eq, 0, 0, 0);
        sgemm_kernel<0><<<grid, NTHREADS>>>(keys,    Wk, k_ptr, Bq * Sq, Eq, Eq, 0, 0, 0);
        sgemm_kernel<0><<<grid, NTHREADS>>>(values,  Wv, v_ptr, Bq * Sq, Eq, Eq, 0, 0, 0);
    }

    // 2) Scores: per batch, [2048,2048] = Q[2048,1024] @ K[2048,1024]^T  (NT)
    {
        dim3 grid(Sq / BN, Sq / BM, Bq);
        sgemm_kernel<1><<<grid, NTHREADS>>>(q_ptr, k_ptr, s_ptr, Sq, Sq, Eq,
                                            (long)Sq * Eq, (long)Sq * Eq, (long)Sq * Sq);
    }

    // 3) Softmax (+ divide by sqrt(E)) over each of the B*S rows
    softmax_scale_kernel<<<Bq * Sq, 256>>>(s_ptr);

    // 4) Output: per batch, [2048,1024] = P[2048,2048] @ V[2048,1024]  (NN)
    {
        dim3 grid(Eq / BN, Sq / BM, Bq);
        sgemm_kernel<0><<<grid, NTHREADS>>>(s_ptr, v_ptr, out, Sq, Eq, Sq,
                                            (long)Sq * Sq, (long)Sq * Eq, (long)Sq * Eq);
    }
    (void)in_sizes; (void)n_in; (void)out_size;
}